// round 14
// baseline (speedup 1.0000x reference)
#include <cuda_runtime.h>
#include <cuda_bf16.h>
#include <mma.h>
#include <cstdint>

using namespace nvcuda;

#define DH 128
#define N_NODES_MAX 50000
#define N_EDGES_MAX 1600000
#define N_GRAPHS_MAX 64
#define TM 128        // nodes per GEMM tile
#define BLD 136       // B smem leading dim (floats)
#define OLD 20        // epilogue staging leading dim (floats)

// ---------------- scratch (device globals: allocation-free) ----------------
// +TM row padding so tail-tile A loads stay in bounds (zeros from .bss)
__device__ float g_bufA[(N_NODES_MAX + TM) * DH];          // gather out = GEMM A (fp32)
__device__ __nv_bfloat16 g_xb[N_NODES_MAX * DH];           // x * dis[n], bf16
__device__ __nv_bfloat16 g_h1b[N_NODES_MAX * DH];          // h1 * dis[n], bf16
__device__ float g_dis[N_NODES_MAX];
__device__ int   g_count[N_NODES_MAX];        // zero on entry; re-zeroed by k_scan
__device__ int   g_off[N_NODES_MAX + 1];
__device__ int   g_cur[N_NODES_MAX];
__device__ int   g_srcs[N_EDGES_MAX];
__device__ float g_pooled[N_GRAPHS_MAX * DH];
__device__ float g_cnt[N_GRAPHS_MAX];

__device__ __forceinline__ void red_add_v4(float4* addr, float4 v) {
    asm volatile("red.global.add.v4.f32 [%0], {%1, %2, %3, %4};"
                 :: "l"(addr), "f"(v.x), "f"(v.y), "f"(v.z), "f"(v.w) : "memory");
}

// ---------------- histogram (int4 vectorized) ----------------
__global__ void k_hist4(const int4* __restrict__ dst4, int nQ) {
    int t = blockIdx.x * blockDim.x + threadIdx.x;
    if (t >= nQ) return;
    int4 d = __ldg(&dst4[t]);
    atomicAdd(&g_count[d.x], 1);
    atomicAdd(&g_count[d.y], 1);
    atomicAdd(&g_count[d.z], 1);
    atomicAdd(&g_count[d.w], 1);
}
__global__ void k_hist_s(const int* __restrict__ dst, int nE) {
    int t = blockIdx.x * blockDim.x + threadIdx.x;
    int e0 = t * 4;
#pragma unroll
    for (int j = 0; j < 4; j++)
        if (e0 + j < nE) atomicAdd(&g_count[dst[e0 + j]], 1);
}

// ------- scan + dis; re-zeros g_count -----
__global__ void __launch_bounds__(1024, 1) k_scan(int nN) {
    __shared__ int sums[1024];
    int t = threadIdx.x;
    int C = (nN + 1023) >> 10;
    int lo = t * C, hi = min(lo + C, nN);

    int s = 0;
    for (int i = lo; i < hi; i++) s += g_count[i];
    sums[t] = s;
    __syncthreads();
    for (int off = 1; off < 1024; off <<= 1) {
        int u = (t >= off) ? sums[t - off] : 0;
        __syncthreads();
        sums[t] += u;
        __syncthreads();
    }
    int run = sums[t] - s;
    for (int i = lo; i < hi; i++) {
        g_off[i] = run;
        g_cur[i] = run;
        int c = g_count[i];
        g_count[i] = 0;
        g_dis[i] = (c > 0) ? rsqrtf((float)c) : 0.f;
        run += c;
    }
    if (t == 1023) g_off[nN] = sums[1023];
}

// -------- fused: CSR build (blocks [0,Bb)) + x pre-scale (rest) ------
__global__ void k_build_scale(const int4* __restrict__ src4, const int4* __restrict__ dst4,
                              int nQ, const float4* __restrict__ x, int nN, int Bb) {
    if ((int)blockIdx.x < Bb) {
        int t = blockIdx.x * blockDim.x + threadIdx.x;
        if (t >= nQ) return;
        int4 d = __ldg(&dst4[t]);
        int4 s = __ldg(&src4[t]);
        int p0 = atomicAdd(&g_cur[d.x], 1);
        int p1 = atomicAdd(&g_cur[d.y], 1);
        int p2 = atomicAdd(&g_cur[d.z], 1);
        int p3 = atomicAdd(&g_cur[d.w], 1);
        g_srcs[p0] = s.x; g_srcs[p1] = s.y; g_srcs[p2] = s.z; g_srcs[p3] = s.w;
    } else {
        int idx = (blockIdx.x - Bb) * blockDim.x + threadIdx.x;
        if (idx < N_GRAPHS_MAX * DH) g_pooled[idx] = 0.f;
        if (idx < N_GRAPHS_MAX) g_cnt[idx] = 0.f;
        int n = idx >> 5;
        if (n >= nN) return;
        int lane = idx & 31;
        float d = g_dis[n];
        float4 v = x[(size_t)n * 32 + lane];
        __nv_bfloat162 p0 = __float22bfloat162_rn(make_float2(v.x * d, v.y * d));
        __nv_bfloat162 p1 = __float22bfloat162_rn(make_float2(v.z * d, v.w * d));
        uint2 u;
        u.x = *reinterpret_cast<unsigned*>(&p0);
        u.y = *reinterpret_cast<unsigned*>(&p1);
        reinterpret_cast<uint2*>(g_xb)[(size_t)n * 32 + lane] = u;
    }
}
__global__ void k_build_scale_s(const int* __restrict__ src, const int* __restrict__ dst,
                                int nE, const float4* __restrict__ x, int nN, int Bb) {
    if ((int)blockIdx.x < Bb) {
        int t = blockIdx.x * blockDim.x + threadIdx.x;
        int e0 = t * 4;
        for (int j = 0; j < 4 && e0 + j < nE; j++) {
            int pos = atomicAdd(&g_cur[dst[e0 + j]], 1);
            g_srcs[pos] = src[e0 + j];
        }
    } else {
        int idx = (blockIdx.x - Bb) * blockDim.x + threadIdx.x;
        if (idx < N_GRAPHS_MAX * DH) g_pooled[idx] = 0.f;
        if (idx < N_GRAPHS_MAX) g_cnt[idx] = 0.f;
        int n = idx >> 5;
        if (n >= nN) return;
        int lane = idx & 31;
        float d = g_dis[n];
        float4 v = x[(size_t)n * 32 + lane];
        __nv_bfloat162 p0 = __float22bfloat162_rn(make_float2(v.x * d, v.y * d));
        __nv_bfloat162 p1 = __float22bfloat162_rn(make_float2(v.z * d, v.w * d));
        uint2 u;
        u.x = *reinterpret_cast<unsigned*>(&p0);
        u.y = *reinterpret_cast<unsigned*>(&p1);
        reinterpret_cast<uint2*>(g_xb)[(size_t)n * 32 + lane] = u;
    }
}

// ---------------- gather: bufA[n] = dis[n] * sum feat_pre[s]  (fp32 out) ------
__device__ __forceinline__ void acc8(float* acc, uint4 u) {
    float2 f;
    f = __bfloat1622float2(*reinterpret_cast<__nv_bfloat162*>(&u.x));
    acc[0] += f.x; acc[1] += f.y;
    f = __bfloat1622float2(*reinterpret_cast<__nv_bfloat162*>(&u.y));
    acc[2] += f.x; acc[3] += f.y;
    f = __bfloat1622float2(*reinterpret_cast<__nv_bfloat162*>(&u.z));
    acc[4] += f.x; acc[5] += f.y;
    f = __bfloat1622float2(*reinterpret_cast<__nv_bfloat162*>(&u.w));
    acc[6] += f.x; acc[7] += f.y;
}

__global__ void __launch_bounds__(256) k_gather(int use_x, int nN) {
    int idx = blockIdx.x * blockDim.x + threadIdx.x;
    int n = idx >> 4;
    if (n >= nN) return;
    int lane = idx & 15;

    const uint4* feat = reinterpret_cast<const uint4*>(use_x ? g_xb : g_h1b);

    int b = g_off[n], e = g_off[n + 1];
    float acc[8] = {0.f, 0.f, 0.f, 0.f, 0.f, 0.f, 0.f, 0.f};

    int i = b;
    for (; i + 8 <= e; i += 8) {
        int s[8];
#pragma unroll
        for (int j = 0; j < 8; j++) s[j] = __ldcs(&g_srcs[i + j]);
        uint4 u[8];
#pragma unroll
        for (int j = 0; j < 8; j++) u[j] = __ldg(&feat[(size_t)s[j] * 16 + lane]);
#pragma unroll
        for (int j = 0; j < 8; j++) acc8(acc, u[j]);
    }
    for (; i + 4 <= e; i += 4) {
        int s0 = __ldcs(&g_srcs[i]),     s1 = __ldcs(&g_srcs[i + 1]);
        int s2 = __ldcs(&g_srcs[i + 2]), s3 = __ldcs(&g_srcs[i + 3]);
        uint4 u0 = __ldg(&feat[(size_t)s0 * 16 + lane]);
        uint4 u1 = __ldg(&feat[(size_t)s1 * 16 + lane]);
        uint4 u2 = __ldg(&feat[(size_t)s2 * 16 + lane]);
        uint4 u3 = __ldg(&feat[(size_t)s3 * 16 + lane]);
        acc8(acc, u0); acc8(acc, u1); acc8(acc, u2); acc8(acc, u3);
    }
    for (; i < e; i++) {
        int s = __ldcs(&g_srcs[i]);
        uint4 u = __ldg(&feat[(size_t)s * 16 + lane]);
        acc8(acc, u);
    }

    float dn = g_dis[n];
#pragma unroll
    for (int j = 0; j < 8; j++) acc[j] *= dn;

    float4* orow = reinterpret_cast<float4*>(&g_bufA[(size_t)n * DH + lane * 8]);
    orow[0] = make_float4(acc[0], acc[1], acc[2], acc[3]);
    orow[1] = make_float4(acc[4], acc[5], acc[6], acc[7]);
}

// ---------------- TF32 WMMA GEMM + bias + ReLU (tile = 128 nodes) --------------
// 8 warps; warp w owns rows [w*16, w*16+16) x all 128 cols (8 fp32 accum frags).
// A read from g_bufA (fp32 global, tail-padded), rounded to tf32 per fragment.
// W rounded to tf32 into smem in two 64-k chunks (stays under 48KB static smem).
// mode 0: h1b[n] = bf16(relu(D+b) * dis[n]);  mode 1: pooled[gid[n]] += relu(D+b).
__global__ void __launch_bounds__(256)
k_gemm_wmma(const float* __restrict__ W, const float* __restrict__ b,
            const int* __restrict__ gid, int nN, int mode) {
    __shared__ float sB[64 * BLD];                  // 34.8 KB (one 64-k chunk)
    __shared__ float bsh[DH];
    __shared__ float sOut[8][16 * OLD];             // 10.2 KB per-warp staging

    int tid = threadIdx.x;
    int wid = tid >> 5, lid = tid & 31;
    int node0 = blockIdx.x * TM;

    if (tid < DH / 4)
        reinterpret_cast<float4*>(bsh)[tid] = reinterpret_cast<const float4*>(b)[tid];

    wmma::fragment<wmma::accumulator, 16, 16, 8, float> acc[8];
#pragma unroll
    for (int j = 0; j < 8; j++) wmma::fill_fragment(acc[j], 0.f);

    const float* Arow = &g_bufA[(size_t)(node0 + wid * 16) * DH];

    for (int kc = 0; kc < 2; kc++) {
        __syncthreads();
        // load W chunk rows [kc*64, kc*64+64), rounded to tf32
        for (int i = tid; i < 64 * DH / 4; i += 256) {
            int k = (i << 2) >> 7;
            int n = (i << 2) & 127;
            float4 w = reinterpret_cast<const float4*>(W + (size_t)kc * 64 * DH)[i];
            float* dstp = &sB[k * BLD + n];
            dstp[0] = wmma::__float_to_tf32(w.x);
            dstp[1] = wmma::__float_to_tf32(w.y);
            dstp[2] = wmma::__float_to_tf32(w.z);
            dstp[3] = wmma::__float_to_tf32(w.w);
        }
        __syncthreads();

#pragma unroll
        for (int k = 0; k < 8; k++) {     // 8 k-steps of 8 within this chunk
            wmma::fragment<wmma::matrix_a, 16, 16, 8, wmma::precision::tf32,
                           wmma::row_major> af;
            wmma::load_matrix_sync(af, Arow + kc * 64 + k * 8, DH);
#pragma unroll
            for (int t = 0; t < af.num_elements; t++)
                af.x[t] = wmma::__float_to_tf32(af.x[t]);
#pragma unroll
            for (int j = 0; j < 8; j++) {
                wmma::fragment<wmma::matrix_b, 16, 16, 8, wmma::precision::tf32,
                               wmma::row_major> bf;
                wmma::load_matrix_sync(bf, &sB[(k * 8) * BLD + j * 16], BLD);
                wmma::mma_sync(acc[j], af, bf, acc[j]);
            }
        }
    }

    // epilogue: per n-tile, stage 16x16 to smem, then 2 lanes per row apply tail ops
    float* ob = sOut[wid];
    int r  = lid >> 1;                        // row within strip
    int hc = (lid & 1) * 8;                   // col half within tile
    int nrow = node0 + wid * 16 + r;
    bool live = (nrow < nN);
    float dn = (live && mode == 0) ? g_dis[nrow] : 0.f;
    int g = (live && mode == 1) ? __ldg(&gid[nrow]) : 0;

#pragma unroll
    for (int j = 0; j < 8; j++) {
        wmma::store_matrix_sync(ob, acc[j], OLD, wmma::mem_row_major);
        __syncwarp();
        if (live) {
            int c0 = j * 16 + hc;
            const float* srcp = &ob[r * OLD + hc];
            float o[8];
#pragma unroll
            for (int t = 0; t < 8; t++)
                o[t] = fmaxf(srcp[t] + bsh[c0 + t], 0.f);
            if (mode == 0) {
                uint4 u;
                __nv_bfloat162 q0 = __float22bfloat162_rn(make_float2(o[0] * dn, o[1] * dn));
                __nv_bfloat162 q1 = __float22bfloat162_rn(make_float2(o[2] * dn, o[3] * dn));
                __nv_bfloat162 q2 = __float22bfloat162_rn(make_float2(o[4] * dn, o[5] * dn));
                __nv_bfloat162 q3 = __float22bfloat162_rn(make_float2(o[6] * dn, o[7] * dn));
                u.x = *reinterpret_cast<unsigned*>(&q0);
                u.y = *reinterpret_cast<unsigned*>(&q1);
                u.z = *reinterpret_cast<unsigned*>(&q2);
                u.w = *reinterpret_cast<unsigned*>(&q3);
                *reinterpret_cast<uint4*>(&g_h1b[(size_t)nrow * DH + c0]) = u;
            } else {
                red_add_v4(reinterpret_cast<float4*>(&g_pooled[(size_t)g * DH + c0]),
                           make_float4(o[0], o[1], o[2], o[3]));
                red_add_v4(reinterpret_cast<float4*>(&g_pooled[(size_t)g * DH + c0 + 4]),
                           make_float4(o[4], o[5], o[6], o[7]));
                if (j == 0 && hc == 0) atomicAdd(&g_cnt[g], 1.0f);
            }
        }
        __syncwarp();
    }
}

// ---------------- classifier ----------------
__global__ void k_logits(const float* __restrict__ Wc, const float* __restrict__ bc,
                         float* __restrict__ out, int nG) {
    int t = threadIdx.x;
    int g = t >> 3, c = t & 7;
    if (g >= nG) return;
    float s = 0.f;
#pragma unroll 8
    for (int k = 0; k < DH; k++)
        s = fmaf(g_pooled[g * DH + k], __ldg(&Wc[k * 8 + c]), s);
    float cnt = fmaxf(g_cnt[g], 1.0f);
    out[g * 8 + c] = s / cnt + bc[c];
}

// ---------------- launch ----------------
extern "C" void kernel_launch(void* const* d_in, const int* in_sizes, int n_in,
                              void* d_out, int out_size) {
    const float* x  = (const float*)d_in[0];
    const int*   ei = (const int*)  d_in[1];
    const int*   gid= (const int*)  d_in[2];
    const float* W1 = (const float*)d_in[3];
    const float* b1 = (const float*)d_in[4];
    const float* W2 = (const float*)d_in[5];
    const float* b2 = (const float*)d_in[6];
    const float* Wc = (const float*)d_in[7];
    const float* bc = (const float*)d_in[8];
    float* out = (float*)d_out;

    int nN = in_sizes[0] / DH;
    int nE = in_sizes[1] / 2;
    int nG = out_size / 8;
    const int* src = ei;
    const int* dst = ei + nE;

    const int T = 256;
    int gN16 = (int)(((long long)nN * 16 + T - 1) / T);
    int scaleBlocks = (int)(((long long)nN * 32 + T - 1) / T);
    int gGemm = (nN + TM - 1) / TM;

    // 1: histogram   2: scan   3: fused build + x pre-scale
    if ((nE & 3) == 0) {
        int nQ = nE >> 2;
        int Bb = (nQ + T - 1) / T;
        k_hist4<<<Bb, T>>>((const int4*)dst, nQ);
        k_scan<<<1, 1024>>>(nN);
        k_build_scale<<<Bb + scaleBlocks, T>>>((const int4*)src, (const int4*)dst,
                                               nQ, (const float4*)x, nN, Bb);
    } else {
        int Bb = (nE / 4 + T) / T;
        k_hist_s<<<Bb, T>>>(dst, nE);
        k_scan<<<1, 1024>>>(nN);
        k_build_scale_s<<<Bb + scaleBlocks, T>>>(src, dst, nE, (const float4*)x, nN, Bb);
    }

    // 4: layer-1 gather   5: TF32 WMMA GEMM1 -> h1b
    k_gather<<<gN16, T>>>(1, nN);
    k_gemm_wmma<<<gGemm, 256>>>(W1, b1, gid, nN, 0);

    // 6: layer-2 gather   7: TF32 WMMA GEMM2 (+fused pooling)
    k_gather<<<gN16, T>>>(0, nN);
    k_gemm_wmma<<<gGemm, 256>>>(W2, b2, gid, nN, 1);

    // 8: classify
    k_logits<<<1, 512>>>(Wc, bc, out, nG);
}

// round 15
// speedup vs baseline: 1.3216x; 1.3216x over previous
#include <cuda_runtime.h>
#include <cuda_bf16.h>
#include <cstdint>

#define DH 128
#define N_NODES_MAX 50000
#define N_EDGES_MAX 1600000
#define N_GRAPHS_MAX 64
#define NPB 64       // nodes per block in GEMM (8 per warp)
#define AST 66       // Ash transposed stride (8B-aligned, low-conflict)
#define STILE 8192   // scan tile (ints)

// ---------------- scratch (device globals: allocation-free) ----------------
__device__ float g_bufA[N_NODES_MAX * DH];           // aggregation result (fp32, GEMM input)
__device__ __nv_bfloat16 g_xb[N_NODES_MAX * DH];     // x * dis[n], bf16 (layer-1 gather src)
__device__ __nv_bfloat16 g_h1b[N_NODES_MAX * DH];    // h1 * dis[n], bf16 (layer-2 gather src)
__device__ float g_dis[N_NODES_MAX];                 // deg^{-1/2}
__device__ int   g_count[N_NODES_MAX];               // zero on entry; re-zeroed by k_scan
__device__ int   g_off[N_NODES_MAX + 1];             // CSR offsets (by dst)
__device__ int   g_cur[N_NODES_MAX];                 // build cursors
__device__ int   g_srcs[N_EDGES_MAX];                // CSR: src node per slot
__device__ float g_pooled[N_GRAPHS_MAX * DH];
__device__ float g_cnt[N_GRAPHS_MAX];

// ---------------- PTX helpers ----------------
__device__ __forceinline__ void red_add_v4(float4* addr, float4 v) {
    asm volatile("red.global.add.v4.f32 [%0], {%1, %2, %3, %4};"
                 :: "l"(addr), "f"(v.x), "f"(v.y), "f"(v.z), "f"(v.w) : "memory");
}
__device__ __forceinline__ unsigned long long pk2(float x, float y) {
    unsigned long long u;
    asm("mov.b64 %0, {%1, %2};" : "=l"(u) : "f"(x), "f"(y));
    return u;
}
__device__ __forceinline__ void upk2(float& x, float& y, unsigned long long u) {
    asm("mov.b64 {%0, %1}, %2;" : "=f"(x), "=f"(y) : "l"(u));
}
__device__ __forceinline__ unsigned long long fma2(unsigned long long a,
                                                   unsigned long long b,
                                                   unsigned long long c) {
    unsigned long long d;
    asm("fma.rn.f32x2 %0, %1, %2, %3;" : "=l"(d) : "l"(a), "l"(b), "l"(c));
    return d;
}
__device__ __forceinline__ unsigned long long addx2(unsigned long long a,
                                                    unsigned long long b) {
    unsigned long long d;
    asm("add.rn.f32x2 %0, %1, %2;" : "=l"(d) : "l"(a), "l"(b));
    return d;
}
// packed bf16x2 word -> packed f32x2 (lo,hi): f32 bits = bf16 bits << 16
__device__ __forceinline__ unsigned long long pklh(unsigned w) {
    unsigned lo = w << 16;
    unsigned hi = w & 0xFFFF0000u;
    unsigned long long r;
    asm("mov.b64 %0, {%1, %2};" : "=l"(r) : "r"(lo), "r"(hi));
    return r;
}

// ---------------- histogram (int4 vectorized, 4 edges/thread) ----------------
// g_count is zero on entry (.bss first call; k_scan re-zeros after each use).
__global__ void k_hist4(const int4* __restrict__ dst4, int nQ) {
    int t = blockIdx.x * blockDim.x + threadIdx.x;
    if (t >= nQ) return;
    int4 d = __ldg(&dst4[t]);
    atomicAdd(&g_count[d.x], 1);
    atomicAdd(&g_count[d.y], 1);
    atomicAdd(&g_count[d.z], 1);
    atomicAdd(&g_count[d.w], 1);
}
__global__ void k_hist_s(const int* __restrict__ dst, int nE) {
    int t = blockIdx.x * blockDim.x + threadIdx.x;
    int e0 = t * 4;
#pragma unroll
    for (int j = 0; j < 4; j++)
        if (e0 + j < nE) atomicAdd(&g_count[dst[e0 + j]], 1);
}

// ---- tiled coalesced single-block scan + dis + count re-zero ----------------
// Tiles of 8192 staged through smem. All global accesses coalesced.
__global__ void __launch_bounds__(1024, 1) k_scan(int nN) {
    __shared__ int tile[STILE];     // 32 KB
    __shared__ int psum[1024];      //  4 KB
    __shared__ int carry;

    int t = threadIdx.x;
    if (t == 0) carry = 0;
    __syncthreads();

    for (int base = 0; base < nN; base += STILE) {
        int cnt = min(STILE, nN - base);

        // coalesced load pass: counts -> smem; also emit dis and zero count
        for (int i = t; i < cnt; i += 1024) {
            int c = g_count[base + i];
            tile[i] = c;
            g_count[base + i] = 0;
            g_dis[base + i] = (c > 0) ? rsqrtf((float)c) : 0.f;
        }
        __syncthreads();

        // per-thread sum of its 8 contiguous counts (keep counts in regs)
        int lo = t * 8;
        int c[8];
        int s = 0;
#pragma unroll
        for (int j = 0; j < 8; j++) {
            int idx = lo + j;
            c[j] = (idx < cnt) ? tile[idx] : 0;
            s += c[j];
        }
        psum[t] = s;
        __syncthreads();

        // Hillis-Steele inclusive scan over 1024 partials
        for (int off = 1; off < 1024; off <<= 1) {
            int u = (t >= off) ? psum[t - off] : 0;
            __syncthreads();
            psum[t] += u;
            __syncthreads();
        }

        int run = carry + psum[t] - s;      // exclusive base for this thread's 8
        __syncthreads();                    // everyone has read carry
        if (t == 1023) carry += psum[1023];

        // stage offsets back into tile (overwrite counts; they're in regs)
#pragma unroll
        for (int j = 0; j < 8; j++) {
            int idx = lo + j;
            if (idx < cnt) tile[idx] = run;
            run += c[j];
        }
        __syncthreads();

        // coalesced store pass: offsets -> g_off, g_cur
        for (int i = t; i < cnt; i += 1024) {
            int o = tile[i];
            g_off[base + i] = o;
            g_cur[base + i] = o;
        }
        __syncthreads();                    // tile reuse + carry visibility
    }
    if (t == 1023) g_off[nN] = carry;
}

// ---------------- CSR build (int4 vectorized) ----------------
__global__ void k_build4(const int4* __restrict__ src4, const int4* __restrict__ dst4, int nQ) {
    int t = blockIdx.x * blockDim.x + threadIdx.x;
    if (t >= nQ) return;
    int4 d = __ldg(&dst4[t]);
    int4 s = __ldg(&src4[t]);
    int p0 = atomicAdd(&g_cur[d.x], 1);
    int p1 = atomicAdd(&g_cur[d.y], 1);
    int p2 = atomicAdd(&g_cur[d.z], 1);
    int p3 = atomicAdd(&g_cur[d.w], 1);
    g_srcs[p0] = s.x; g_srcs[p1] = s.y; g_srcs[p2] = s.z; g_srcs[p3] = s.w;
}
__global__ void k_build_s(const int* __restrict__ src, const int* __restrict__ dst, int nE) {
    int t = blockIdx.x * blockDim.x + threadIdx.x;
    int e0 = t * 4;
    for (int j = 0; j < 4 && e0 + j < nE; j++) {
        int pos = atomicAdd(&g_cur[dst[e0 + j]], 1);
        g_srcs[pos] = src[e0 + j];
    }
}

// -------- pre-scale x: xb[n] = bf16(x[n]*dis[n]); zeros pooled/cnt --------
__global__ void k_scale_x(const float4* __restrict__ x, int nN) {
    int idx = blockIdx.x * blockDim.x + threadIdx.x;
    if (idx < N_GRAPHS_MAX * DH) g_pooled[idx] = 0.f;
    if (idx < N_GRAPHS_MAX) g_cnt[idx] = 0.f;
    int n = idx >> 5;
    if (n >= nN) return;
    int lane = idx & 31;
    float d = g_dis[n];
    float4 v = x[(size_t)n * 32 + lane];
    __nv_bfloat162 p0 = __float22bfloat162_rn(make_float2(v.x * d, v.y * d));
    __nv_bfloat162 p1 = __float22bfloat162_rn(make_float2(v.z * d, v.w * d));
    uint2 u;
    u.x = *reinterpret_cast<unsigned*>(&p0);
    u.y = *reinterpret_cast<unsigned*>(&p1);
    reinterpret_cast<uint2*>(g_xb)[(size_t)n * 32 + lane] = u;
}

// ---------------- gather: bufA[n] = dis[n] * sum feat_pre[s]  (fp32 out) ------
// 2 nodes/warp, 16 lanes/node, one uint4 (8 bf16) per lane per edge.
// Packed f32x2 accumulation: per pair, 2 LOP + 1 add.rn.f32x2.
__device__ __forceinline__ void acc4p(unsigned long long* a, uint4 u) {
    a[0] = addx2(a[0], pklh(u.x));
    a[1] = addx2(a[1], pklh(u.y));
    a[2] = addx2(a[2], pklh(u.z));
    a[3] = addx2(a[3], pklh(u.w));
}

__global__ void __launch_bounds__(256) k_gather(int use_x, int nN) {
    int idx = blockIdx.x * blockDim.x + threadIdx.x;
    int n = idx >> 4;
    if (n >= nN) return;
    unsigned lane = idx & 15;

    const uint4* feat = reinterpret_cast<const uint4*>(use_x ? g_xb : g_h1b);

    int b = g_off[n], e = g_off[n + 1];
    unsigned long long a[4] = {0ULL, 0ULL, 0ULL, 0ULL};   // bits of (0.f,0.f)

    int i = b;
    for (; i + 8 <= e; i += 8) {
        unsigned s[8];
#pragma unroll
        for (int j = 0; j < 8; j++) s[j] = (unsigned)__ldcs(&g_srcs[i + j]);
        uint4 u[8];
#pragma unroll
        for (int j = 0; j < 8; j++) u[j] = __ldg(&feat[(s[j] << 4) + lane]);
#pragma unroll
        for (int j = 0; j < 8; j++) acc4p(a, u[j]);
    }
    for (; i + 4 <= e; i += 4) {
        unsigned s0 = (unsigned)__ldcs(&g_srcs[i]);
        unsigned s1 = (unsigned)__ldcs(&g_srcs[i + 1]);
        unsigned s2 = (unsigned)__ldcs(&g_srcs[i + 2]);
        unsigned s3 = (unsigned)__ldcs(&g_srcs[i + 3]);
        uint4 u0 = __ldg(&feat[(s0 << 4) + lane]);
        uint4 u1 = __ldg(&feat[(s1 << 4) + lane]);
        uint4 u2 = __ldg(&feat[(s2 << 4) + lane]);
        uint4 u3 = __ldg(&feat[(s3 << 4) + lane]);
        acc4p(a, u0); acc4p(a, u1); acc4p(a, u2); acc4p(a, u3);
    }
    for (; i < e; i++) {
        unsigned s = (unsigned)__ldcs(&g_srcs[i]);
        uint4 u = __ldg(&feat[(s << 4) + lane]);
        acc4p(a, u);
    }

    float dn = g_dis[n];
    float o[8];
    upk2(o[0], o[1], a[0]);
    upk2(o[2], o[3], a[1]);
    upk2(o[4], o[5], a[2]);
    upk2(o[6], o[7], a[3]);
#pragma unroll
    for (int j = 0; j < 8; j++) o[j] *= dn;

    float4* orow = reinterpret_cast<float4*>(&g_bufA[(size_t)n * DH + lane * 8]);
    orow[0] = make_float4(o[0], o[1], o[2], o[3]);
    orow[1] = make_float4(o[4], o[5], o[6], o[7]);
}

// ---------------- GEMM + bias + ReLU (FFMA2, 8 nodes/warp — R9 proven) --------
// mode 0: write bf16(relu(.)*dis[n]) to g_h1b                 (layer 1)
// mode 1: fused pooling — red_add relu(.) into g_pooled[gid]  (layer 2)
__global__ void __launch_bounds__(256, 2)
k_gemm_relu(const float* __restrict__ W, const float* __restrict__ b,
            const int* __restrict__ gid, int nN, int mode) {
    __shared__ float Wsh[32 * DH];       // 16 KB: W rows k0..k0+31
    __shared__ float Ash[32 * AST];      // 8.25 KB: A chunk TRANSPOSED [kk][node]
    __shared__ float bsh[DH];

    const float* A = g_bufA;

    int tid = threadIdx.x;
    int node0 = blockIdx.x * NPB;
    if (tid < DH / 4)
        reinterpret_cast<float4*>(bsh)[tid] = reinterpret_cast<const float4*>(b)[tid];

    int warp = tid >> 5, lane = tid & 31;

    unsigned long long accP[4][4];
#pragma unroll
    for (int p = 0; p < 4; p++)
#pragma unroll
        for (int c = 0; c < 4; c++) accP[p][c] = 0ULL;

    for (int k0 = 0; k0 < DH; k0 += 32) {
        __syncthreads();
#pragma unroll
        for (int i = tid; i < 32 * DH / 4; i += 256)
            reinterpret_cast<float4*>(Wsh)[i] =
                reinterpret_cast<const float4*>(W + (size_t)k0 * DH)[i];
#pragma unroll
        for (int i = tid; i < NPB * 8; i += 256) {
            int nl = i >> 3;
            int j  = i & 7;
            int n = node0 + nl;
            float4 av = make_float4(0.f, 0.f, 0.f, 0.f);
            if (n < nN)
                av = *reinterpret_cast<const float4*>(&A[(size_t)n * DH + k0 + (j << 2)]);
            Ash[(j * 4 + 0) * AST + nl] = av.x;
            Ash[(j * 4 + 1) * AST + nl] = av.y;
            Ash[(j * 4 + 2) * AST + nl] = av.z;
            Ash[(j * 4 + 3) * AST + nl] = av.w;
        }
        __syncthreads();

#pragma unroll 8
        for (int kk = 0; kk < 32; kk++) {
            float4 w = *reinterpret_cast<const float4*>(&Wsh[kk * DH + lane * 4]);
            unsigned long long wd0 = pk2(w.x, w.x);
            unsigned long long wd1 = pk2(w.y, w.y);
            unsigned long long wd2 = pk2(w.z, w.z);
            unsigned long long wd3 = pk2(w.w, w.w);
            const float* Ar = &Ash[kk * AST + warp * 8];
#pragma unroll
            for (int p = 0; p < 4; p++) {
                unsigned long long pa =
                    *reinterpret_cast<const unsigned long long*>(&Ar[2 * p]);
                accP[p][0] = fma2(pa, wd0, accP[p][0]);
                accP[p][1] = fma2(pa, wd1, accP[p][1]);
                accP[p][2] = fma2(pa, wd2, accP[p][2]);
                accP[p][3] = fma2(pa, wd3, accP[p][3]);
            }
        }
    }

    float4 bb = *reinterpret_cast<const float4*>(&bsh[lane * 4]);
#pragma unroll
    for (int p = 0; p < 4; p++) {
        float a0[4], a1[4];
#pragma unroll
        for (int c = 0; c < 4; c++) upk2(a0[c], a1[c], accP[p][c]);
#pragma unroll
        for (int half = 0; half < 2; half++) {
            int n = node0 + warp * 8 + 2 * p + half;
            if (n >= nN) continue;
            const float* av = half ? a1 : a0;
            float4 o;
            o.x = fmaxf(av[0] + bb.x, 0.f);
            o.y = fmaxf(av[1] + bb.y, 0.f);
            o.z = fmaxf(av[2] + bb.z, 0.f);
            o.w = fmaxf(av[3] + bb.w, 0.f);
            if (mode == 0) {
                float d = g_dis[n];
                __nv_bfloat162 p0 = __float22bfloat162_rn(make_float2(o.x * d, o.y * d));
                __nv_bfloat162 p1 = __float22bfloat162_rn(make_float2(o.z * d, o.w * d));
                uint2 u;
                u.x = *reinterpret_cast<unsigned*>(&p0);
                u.y = *reinterpret_cast<unsigned*>(&p1);
                reinterpret_cast<uint2*>(g_h1b)[(size_t)n * 32 + lane] = u;
            } else {
                int g = __ldg(&gid[n]);
                red_add_v4(reinterpret_cast<float4*>(&g_pooled[(size_t)g * DH]) + lane, o);
                if (lane == 0) atomicAdd(&g_cnt[g], 1.0f);
            }
        }
    }
}

// ---------------- classifier ----------------
__global__ void k_logits(const float* __restrict__ Wc, const float* __restrict__ bc,
                         float* __restrict__ out, int nG) {
    int t = threadIdx.x;
    int g = t >> 3, c = t & 7;
    if (g >= nG) return;
    float s = 0.f;
#pragma unroll 8
    for (int k = 0; k < DH; k++)
        s = fmaf(g_pooled[g * DH + k], __ldg(&Wc[k * 8 + c]), s);
    float cnt = fmaxf(g_cnt[g], 1.0f);
    out[g * 8 + c] = s / cnt + bc[c];
}

// ---------------- launch ----------------
extern "C" void kernel_launch(void* const* d_in, const int* in_sizes, int n_in,
                              void* d_out, int out_size) {
    const float* x  = (const float*)d_in[0];
    const int*   ei = (const int*)  d_in[1];
    const int*   gid= (const int*)  d_in[2];
    const float* W1 = (const float*)d_in[3];
    const float* b1 = (const float*)d_in[4];
    const float* W2 = (const float*)d_in[5];
    const float* b2 = (const float*)d_in[6];
    const float* Wc = (const float*)d_in[7];
    const float* bc = (const float*)d_in[8];
    float* out = (float*)d_out;

    int nN = in_sizes[0] / DH;
    int nE = in_sizes[1] / 2;
    int nG = out_size / 8;
    const int* src = ei;
    const int* dst = ei + nE;

    const int T = 256;
    int gN16 = (int)(((long long)nN * 16 + T - 1) / T);
    int gN32 = (int)(((long long)nN * 32 + T - 1) / T);
    int gGemm = (nN + NPB - 1) / NPB;

    // 1: histogram   2: tiled scan   3: x pre-scale   4: CSR build (profiled slot)
    if ((nE & 3) == 0) {
        int nQ = nE >> 2;
        int gQ = (nQ + T - 1) / T;
        k_hist4<<<gQ, T>>>((const int4*)dst, nQ);
        k_scan<<<1, 1024>>>(nN);
        k_scale_x<<<gN32, T>>>((const float4*)x, nN);
        k_build4<<<gQ, T>>>((const int4*)src, (const int4*)dst, nQ);
    } else {
        int gE4 = (nE / 4 + T) / T;
        k_hist_s<<<gE4, T>>>(dst, nE);
        k_scan<<<1, 1024>>>(nN);
        k_scale_x<<<gN32, T>>>((const float4*)x, nN);
        k_build_s<<<gE4, T>>>(src, dst, nE);
    }

    // 5: layer-1 gather   6: GEMM1 -> h1b
    k_gather<<<gN16, T>>>(1, nN);
    k_gemm_relu<<<gGemm, T>>>(W1, b1, gid, nN, 0);

    // 7: layer-2 gather   8: GEMM2 (+fused pooling)
    k_gather<<<gN16, T>>>(0, nN);
    k_gemm_relu<<<gGemm, T>>>(W2, b2, gid, nN, 1);

    // 9: classify
    k_logits<<<1, 512>>>(Wc, bc, out, nG);
}

// round 16
// speedup vs baseline: 1.3476x; 1.0197x over previous
#include <cuda_runtime.h>
#include <cuda_bf16.h>
#include <cuda_fp16.h>
#include <mma.h>
#include <cstdint>

using namespace nvcuda;

#define DH 128
#define N_NODES_MAX 50000
#define N_EDGES_MAX 1600000
#define N_GRAPHS_MAX 64
#define TM 128       // nodes per GEMM tile
#define ALD 136      // A smem leading dim (halfs)
#define WLD 136      // W smem leading dim (halfs)
#define OLD 20       // epilogue staging leading dim (floats)
#define STILE 8192   // scan tile (ints)

// ---------------- scratch (device globals: allocation-free) ----------------
// +TM row padding: GEMM tail tile reads rows >= nN; they stay .bss-zero forever
// (gather only writes rows < nN).
__device__ float g_bufA[(N_NODES_MAX + TM) * DH];    // aggregation result (fp32)
__device__ __nv_bfloat16 g_xb[N_NODES_MAX * DH];     // x * dis[n], bf16 (layer-1 gather src)
__device__ __nv_bfloat16 g_h1b[N_NODES_MAX * DH];    // h1 * dis[n], bf16 (layer-2 gather src)
__device__ float g_dis[N_NODES_MAX];                 // deg^{-1/2}
__device__ int   g_count[N_NODES_MAX];               // zero on entry; re-zeroed by k_scan
__device__ int   g_off[N_NODES_MAX + 1];             // CSR offsets (by dst)
__device__ int   g_cur[N_NODES_MAX];                 // build cursors
__device__ int   g_srcs[N_EDGES_MAX];                // CSR: src node per slot
__device__ float g_pooled[N_GRAPHS_MAX * DH];
__device__ float g_cnt[N_GRAPHS_MAX];

// ---------------- PTX helpers ----------------
__device__ __forceinline__ void red_add_v4(float4* addr, float4 v) {
    asm volatile("red.global.add.v4.f32 [%0], {%1, %2, %3, %4};"
                 :: "l"(addr), "f"(v.x), "f"(v.y), "f"(v.z), "f"(v.w) : "memory");
}
__device__ __forceinline__ void upk2(float& x, float& y, unsigned long long u) {
    asm("mov.b64 {%0, %1}, %2;" : "=f"(x), "=f"(y) : "l"(u));
}
__device__ __forceinline__ unsigned long long addx2(unsigned long long a,
                                                    unsigned long long b) {
    unsigned long long d;
    asm("add.rn.f32x2 %0, %1, %2;" : "=l"(d) : "l"(a), "l"(b));
    return d;
}
// packed bf16x2 word -> packed f32x2 (lo,hi): f32 bits = bf16 bits << 16
__device__ __forceinline__ unsigned long long pklh(unsigned w) {
    unsigned lo = w << 16;
    unsigned hi = w & 0xFFFF0000u;
    unsigned long long r;
    asm("mov.b64 %0, {%1, %2};" : "=l"(r) : "r"(lo), "r"(hi));
    return r;
}

// ---------------- histogram (int4 vectorized, 4 edges/thread) ----------------
__global__ void k_hist4(const int4* __restrict__ dst4, int nQ) {
    int t = blockIdx.x * blockDim.x + threadIdx.x;
    if (t >= nQ) return;
    int4 d = __ldg(&dst4[t]);
    atomicAdd(&g_count[d.x], 1);
    atomicAdd(&g_count[d.y], 1);
    atomicAdd(&g_count[d.z], 1);
    atomicAdd(&g_count[d.w], 1);
}
__global__ void k_hist_s(const int* __restrict__ dst, int nE) {
    int t = blockIdx.x * blockDim.x + threadIdx.x;
    int e0 = t * 4;
#pragma unroll
    for (int j = 0; j < 4; j++)
        if (e0 + j < nE) atomicAdd(&g_count[dst[e0 + j]], 1);
}

// ---- tiled coalesced single-block scan + dis + count re-zero ----------------
__global__ void __launch_bounds__(1024, 1) k_scan(int nN) {
    __shared__ int tile[STILE];     // 32 KB
    __shared__ int psum[1024];      //  4 KB
    __shared__ int carry;

    int t = threadIdx.x;
    if (t == 0) carry = 0;
    __syncthreads();

    for (int base = 0; base < nN; base += STILE) {
        int cnt = min(STILE, nN - base);

        for (int i = t; i < cnt; i += 1024) {
            int c = g_count[base + i];
            tile[i] = c;
            g_count[base + i] = 0;
            g_dis[base + i] = (c > 0) ? rsqrtf((float)c) : 0.f;
        }
        __syncthreads();

        int lo = t * 8;
        int c[8];
        int s = 0;
#pragma unroll
        for (int j = 0; j < 8; j++) {
            int idx = lo + j;
            c[j] = (idx < cnt) ? tile[idx] : 0;
            s += c[j];
        }
        psum[t] = s;
        __syncthreads();

        for (int off = 1; off < 1024; off <<= 1) {
            int u = (t >= off) ? psum[t - off] : 0;
            __syncthreads();
            psum[t] += u;
            __syncthreads();
        }

        int run = carry + psum[t] - s;
        __syncthreads();
        if (t == 1023) carry += psum[1023];

#pragma unroll
        for (int j = 0; j < 8; j++) {
            int idx = lo + j;
            if (idx < cnt) tile[idx] = run;
            run += c[j];
        }
        __syncthreads();

        for (int i = t; i < cnt; i += 1024) {
            int o = tile[i];
            g_off[base + i] = o;
            g_cur[base + i] = o;
        }
        __syncthreads();
    }
    if (t == 1023) g_off[nN] = carry;
}

// ---------------- CSR build (int4 vectorized) ----------------
__global__ void k_build4(const int4* __restrict__ src4, const int4* __restrict__ dst4, int nQ) {
    int t = blockIdx.x * blockDim.x + threadIdx.x;
    if (t >= nQ) return;
    int4 d = __ldg(&dst4[t]);
    int4 s = __ldg(&src4[t]);
    int p0 = atomicAdd(&g_cur[d.x], 1);
    int p1 = atomicAdd(&g_cur[d.y], 1);
    int p2 = atomicAdd(&g_cur[d.z], 1);
    int p3 = atomicAdd(&g_cur[d.w], 1);
    g_srcs[p0] = s.x; g_srcs[p1] = s.y; g_srcs[p2] = s.z; g_srcs[p3] = s.w;
}
__global__ void k_build_s(const int* __restrict__ src, const int* __restrict__ dst, int nE) {
    int t = blockIdx.x * blockDim.x + threadIdx.x;
    int e0 = t * 4;
    for (int j = 0; j < 4 && e0 + j < nE; j++) {
        int pos = atomicAdd(&g_cur[dst[e0 + j]], 1);
        g_srcs[pos] = src[e0 + j];
    }
}

// -------- pre-scale x: xb[n] = bf16(x[n]*dis[n]); zeros pooled/cnt --------
__global__ void k_scale_x(const float4* __restrict__ x, int nN) {
    int idx = blockIdx.x * blockDim.x + threadIdx.x;
    if (idx < N_GRAPHS_MAX * DH) g_pooled[idx] = 0.f;
    if (idx < N_GRAPHS_MAX) g_cnt[idx] = 0.f;
    int n = idx >> 5;
    if (n >= nN) return;
    int lane = idx & 31;
    float d = g_dis[n];
    float4 v = x[(size_t)n * 32 + lane];
    __nv_bfloat162 p0 = __float22bfloat162_rn(make_float2(v.x * d, v.y * d));
    __nv_bfloat162 p1 = __float22bfloat162_rn(make_float2(v.z * d, v.w * d));
    uint2 u;
    u.x = *reinterpret_cast<unsigned*>(&p0);
    u.y = *reinterpret_cast<unsigned*>(&p1);
    reinterpret_cast<uint2*>(g_xb)[(size_t)n * 32 + lane] = u;
}

// ---------------- gather: bufA[n] = dis[n] * sum feat_pre[s]  (fp32 out) ------
__device__ __forceinline__ void acc4p(unsigned long long* a, uint4 u) {
    a[0] = addx2(a[0], pklh(u.x));
    a[1] = addx2(a[1], pklh(u.y));
    a[2] = addx2(a[2], pklh(u.z));
    a[3] = addx2(a[3], pklh(u.w));
}

__global__ void __launch_bounds__(256) k_gather(int use_x, int nN) {
    int idx = blockIdx.x * blockDim.x + threadIdx.x;
    int n = idx >> 4;
    if (n >= nN) return;
    unsigned lane = idx & 15;

    const uint4* feat = reinterpret_cast<const uint4*>(use_x ? g_xb : g_h1b);

    int b = g_off[n], e = g_off[n + 1];
    unsigned long long a[4] = {0ULL, 0ULL, 0ULL, 0ULL};

    int i = b;
    for (; i + 8 <= e; i += 8) {
        unsigned s[8];
#pragma unroll
        for (int j = 0; j < 8; j++) s[j] = (unsigned)__ldcs(&g_srcs[i + j]);
        uint4 u[8];
#pragma unroll
        for (int j = 0; j < 8; j++) u[j] = __ldg(&feat[(s[j] << 4) + lane]);
#pragma unroll
        for (int j = 0; j < 8; j++) acc4p(a, u[j]);
    }
    for (; i + 4 <= e; i += 4) {
        unsigned s0 = (unsigned)__ldcs(&g_srcs[i]);
        unsigned s1 = (unsigned)__ldcs(&g_srcs[i + 1]);
        unsigned s2 = (unsigned)__ldcs(&g_srcs[i + 2]);
        unsigned s3 = (unsigned)__ldcs(&g_srcs[i + 3]);
        uint4 u0 = __ldg(&feat[(s0 << 4) + lane]);
        uint4 u1 = __ldg(&feat[(s1 << 4) + lane]);
        uint4 u2 = __ldg(&feat[(s2 << 4) + lane]);
        uint4 u3 = __ldg(&feat[(s3 << 4) + lane]);
        acc4p(a, u0); acc4p(a, u1); acc4p(a, u2); acc4p(a, u3);
    }
    for (; i < e; i++) {
        unsigned s = (unsigned)__ldcs(&g_srcs[i]);
        uint4 u = __ldg(&feat[(s << 4) + lane]);
        acc4p(a, u);
    }

    float dn = g_dis[n];
    float o[8];
    upk2(o[0], o[1], a[0]);
    upk2(o[2], o[3], a[1]);
    upk2(o[4], o[5], a[2]);
    upk2(o[6], o[7], a[3]);
#pragma unroll
    for (int j = 0; j < 8; j++) o[j] *= dn;

    float4* orow = reinterpret_cast<float4*>(&g_bufA[(size_t)n * DH + lane * 8]);
    orow[0] = make_float4(o[0], o[1], o[2], o[3]);
    orow[1] = make_float4(o[4], o[5], o[6], o[7]);
}

// ---------------- fp16 WMMA GEMM + bias + ReLU (tile = 128 nodes) -------------
// 8 warps; warp w owns rows [w*16, w*16+16) x all 128 cols (8 fp32 accum frags).
// A tile staged fp32 -> fp16 smem ONCE (34.8 KB); W in 4 chunks of 32 k rows,
// fp32 -> fp16 (8.7 KB). Epilogue staging reuses the A buffer. 43 KB static.
// mode 0: h1b[n] = bf16(relu(D+b) * dis[n]);  mode 1: pooled[gid[n]] += relu(D+b).
__global__ void __launch_bounds__(256, 2)
k_gemm_hmma(const float* __restrict__ W, const float* __restrict__ b,
            const int* __restrict__ gid, int nN, int mode) {
    __shared__ __half sA[TM * ALD];         // 34.8 KB (A tile; later epilogue staging)
    __shared__ __half sW[32 * WLD];         //  8.7 KB (W k-chunk)
    __shared__ float bsh[DH];

    int tid = threadIdx.x;
    int wid = tid >> 5, lid = tid & 31;
    int node0 = blockIdx.x * TM;

    if (tid < DH / 4)
        reinterpret_cast<float4*>(bsh)[tid] = reinterpret_cast<const float4*>(b)[tid];

    // stage A tile: 128 rows x 128 k, fp32 -> fp16  (rows >= nN read zero padding)
    {
        const float4* asrc = reinterpret_cast<const float4*>(
            &g_bufA[(size_t)node0 * DH]);
        for (int i = tid; i < TM * DH / 4; i += 256) {
            int r = i >> 5;            // i / 32 (32 float4 per row)
            int c = (i & 31) << 2;     // col
            float4 v = asrc[i];
            __half2 h0 = __floats2half2_rn(v.x, v.y);
            __half2 h1 = __floats2half2_rn(v.z, v.w);
            uint2 u;
            u.x = *reinterpret_cast<unsigned*>(&h0);
            u.y = *reinterpret_cast<unsigned*>(&h1);
            *reinterpret_cast<uint2*>(&sA[r * ALD + c]) = u;
        }
    }

    wmma::fragment<wmma::accumulator, 16, 16, 16, float> acc[8];
#pragma unroll
    for (int j = 0; j < 8; j++) wmma::fill_fragment(acc[j], 0.f);

    for (int kc = 0; kc < 4; kc++) {
        __syncthreads();
        // stage W chunk rows [kc*32, +32), fp32 -> fp16
        const float4* wsrc = reinterpret_cast<const float4*>(W + (size_t)kc * 32 * DH);
        for (int i = tid; i < 32 * DH / 4; i += 256) {
            int k = i >> 5;
            int c = (i & 31) << 2;
            float4 v = wsrc[i];
            __half2 h0 = __floats2half2_rn(v.x, v.y);
            __half2 h1 = __floats2half2_rn(v.z, v.w);
            uint2 u;
            u.x = *reinterpret_cast<unsigned*>(&h0);
            u.y = *reinterpret_cast<unsigned*>(&h1);
            *reinterpret_cast<uint2*>(&sW[k * WLD + c]) = u;
        }
        __syncthreads();

#pragma unroll
        for (int ks = 0; ks < 2; ks++) {    // two k=16 steps per chunk
            wmma::fragment<wmma::matrix_a, 16, 16, 16, __half, wmma::row_major> af;
            wmma::load_matrix_sync(af, &sA[(wid * 16) * ALD + kc * 32 + ks * 16], ALD);
#pragma unroll
            for (int j = 0; j < 8; j++) {
                wmma::fragment<wmma::matrix_b, 16, 16, 16, __half, wmma::row_major> bf;
                wmma::load_matrix_sync(bf, &sW[(ks * 16) * WLD + j * 16], WLD);
                wmma::mma_sync(acc[j], af, bf, acc[j]);
            }
        }
    }

    // epilogue: reuse sA as fp32 staging (all A reads are done; sync first)
    __syncthreads();
    float* stage = reinterpret_cast<float*>(sA);
    float* ob = stage + wid * (16 * OLD);
    int r  = lid >> 1;
    int hc = (lid & 1) * 8;
    int nrow = node0 + wid * 16 + r;
    bool live = (nrow < nN);
    float dn = (live && mode == 0) ? g_dis[nrow] : 0.f;
    int g = (live && mode == 1) ? __ldg(&gid[nrow]) : 0;

#pragma unroll
    for (int j = 0; j < 8; j++) {
        wmma::store_matrix_sync(ob, acc[j], OLD, wmma::mem_row_major);
        __syncwarp();
        if (live) {
            int c0 = j * 16 + hc;
            const float* srcp = &ob[r * OLD + hc];
            float o[8];
#pragma unroll
            for (int t = 0; t < 8; t++)
                o[t] = fmaxf(srcp[t] + bsh[c0 + t], 0.f);
            if (mode == 0) {
                uint4 u;
                __nv_bfloat162 q0 = __float22bfloat162_rn(make_float2(o[0] * dn, o[1] * dn));
                __nv_bfloat162 q1 = __float22bfloat162_rn(make_float2(o[2] * dn, o[3] * dn));
                __nv_bfloat162 q2 = __float22bfloat162_rn(make_float2(o[4] * dn, o[5] * dn));
                __nv_bfloat162 q3 = __float22bfloat162_rn(make_float2(o[6] * dn, o[7] * dn));
                u.x = *reinterpret_cast<unsigned*>(&q0);
                u.y = *reinterpret_cast<unsigned*>(&q1);
                u.z = *reinterpret_cast<unsigned*>(&q2);
                u.w = *reinterpret_cast<unsigned*>(&q3);
                *reinterpret_cast<uint4*>(&g_h1b[(size_t)nrow * DH + c0]) = u;
            } else {
                red_add_v4(reinterpret_cast<float4*>(&g_pooled[(size_t)g * DH + c0]),
                           make_float4(o[0], o[1], o[2], o[3]));
                red_add_v4(reinterpret_cast<float4*>(&g_pooled[(size_t)g * DH + c0 + 4]),
                           make_float4(o[4], o[5], o[6], o[7]));
                if (j == 0 && hc == 0) atomicAdd(&g_cnt[g], 1.0f);
            }
        }
        __syncwarp();
    }
}

// ---------------- classifier ----------------
__global__ void k_logits(const float* __restrict__ Wc, const float* __restrict__ bc,
                         float* __restrict__ out, int nG) {
    int t = threadIdx.x;
    int g = t >> 3, c = t & 7;
    if (g >= nG) return;
    float s = 0.f;
#pragma unroll 8
    for (int k = 0; k < DH; k++)
        s = fmaf(g_pooled[g * DH + k], __ldg(&Wc[k * 8 + c]), s);
    float cnt = fmaxf(g_cnt[g], 1.0f);
    out[g * 8 + c] = s / cnt + bc[c];
}

// ---------------- launch ----------------
extern "C" void kernel_launch(void* const* d_in, const int* in_sizes, int n_in,
                              void* d_out, int out_size) {
    const float* x  = (const float*)d_in[0];
    const int*   ei = (const int*)  d_in[1];
    const int*   gid= (const int*)  d_in[2];
    const float* W1 = (const float*)d_in[3];
    const float* b1 = (const float*)d_in[4];
    const float* W2 = (const float*)d_in[5];
    const float* b2 = (const float*)d_in[6];
    const float* Wc = (const float*)d_in[7];
    const float* bc = (const float*)d_in[8];
    float* out = (float*)d_out;

    int nN = in_sizes[0] / DH;
    int nE = in_sizes[1] / 2;
    int nG = out_size / 8;
    const int* src = ei;
    const int* dst = ei + nE;

    const int T = 256;
    int gN16 = (int)(((long long)nN * 16 + T - 1) / T);
    int gN32 = (int)(((long long)nN * 32 + T - 1) / T);
    int gGemm = (nN + TM - 1) / TM;

    // 1: histogram   2: tiled scan   3: x pre-scale   4: CSR build (profiled slot)
    if ((nE & 3) == 0) {
        int nQ = nE >> 2;
        int gQ = (nQ + T - 1) / T;
        k_hist4<<<gQ, T>>>((const int4*)dst, nQ);
        k_scan<<<1, 1024>>>(nN);
        k_scale_x<<<gN32, T>>>((const float4*)x, nN);
        k_build4<<<gQ, T>>>((const int4*)src, (const int4*)dst, nQ);
    } else {
        int gE4 = (nE / 4 + T) / T;
        k_hist_s<<<gE4, T>>>(dst, nE);
        k_scan<<<1, 1024>>>(nN);
        k_scale_x<<<gN32, T>>>((const float4*)x, nN);
        k_build_s<<<gE4, T>>>(src, dst, nE);
    }

    // 5: layer-1 gather   6: fp16 WMMA GEMM1 -> h1b
    k_gather<<<gN16, T>>>(1, nN);
    k_gemm_hmma<<<gGemm, T>>>(W1, b1, gid, nN, 0);

    // 7: layer-2 gather   8: fp16 WMMA GEMM2 (+fused pooling)
    k_gather<<<gN16, T>>>(0, nN);
    k_gemm_hmma<<<gGemm, T>>>(W2, b2, gid, nN, 1);

    // 9: classify
    k_logits<<<1, 512>>>(Wc, bc, out, nG);
}

// round 17
// speedup vs baseline: 1.5708x; 1.1656x over previous
#include <cuda_runtime.h>
#include <cuda_bf16.h>
#include <cuda_fp16.h>
#include <mma.h>
#include <cstdint>

using namespace nvcuda;

#define DH 128
#define N_NODES_MAX 50000
#define N_EDGES_MAX 1600000
#define N_GRAPHS_MAX 64
#define TM 128       // nodes per GEMM tile
#define ALD 136      // A smem leading dim (halfs)
#define WLD 136      // W smem leading dim (halfs)
#define OLD 20       // epilogue staging leading dim (floats)
#define STILE 8192   // scan tile (ints)

// ---------------- scratch (device globals: allocation-free) ----------------
// +TM row padding: GEMM tail tile reads rows >= nN; they stay .bss-zero forever
// (gather only writes rows < nN).
__device__ float g_bufA[(N_NODES_MAX + TM) * DH];    // aggregation result (fp32)
__device__ __nv_bfloat16 g_xb[N_NODES_MAX * DH];     // x * dis[n], bf16 (layer-1 gather src)
__device__ __nv_bfloat16 g_h1b[N_NODES_MAX * DH];    // h1 * dis[n], bf16 (layer-2 gather src)
__device__ float g_dis[N_NODES_MAX];                 // deg^{-1/2}
__device__ int   g_count[N_NODES_MAX];               // zero on entry; re-zeroed by k_scan
__device__ int   g_off[N_NODES_MAX + 1];             // CSR offsets (by dst)
__device__ int   g_cur[N_NODES_MAX];                 // build cursors
__device__ int   g_srcs[N_EDGES_MAX];                // CSR: src node per slot
__device__ float g_pooled[N_GRAPHS_MAX * DH];

// ---------------- PTX helpers ----------------
__device__ __forceinline__ void red_add_f32(float* addr, float v) {
    asm volatile("red.global.add.f32 [%0], %1;" :: "l"(addr), "f"(v) : "memory");
}
__device__ __forceinline__ void upk2(float& x, float& y, unsigned long long u) {
    asm("mov.b64 {%0, %1}, %2;" : "=f"(x), "=f"(y) : "l"(u));
}
__device__ __forceinline__ unsigned long long addx2(unsigned long long a,
                                                    unsigned long long b) {
    unsigned long long d;
    asm("add.rn.f32x2 %0, %1, %2;" : "=l"(d) : "l"(a), "l"(b));
    return d;
}
// packed bf16x2 word -> packed f32x2 (lo,hi): f32 bits = bf16 bits << 16
__device__ __forceinline__ unsigned long long pklh(unsigned w) {
    unsigned lo = w << 16;
    unsigned hi = w & 0xFFFF0000u;
    unsigned long long r;
    asm("mov.b64 %0, {%1, %2};" : "=l"(r) : "r"(lo), "r"(hi));
    return r;
}

// ---------------- histogram (int4 vectorized, 4 edges/thread) ----------------
__global__ void k_hist4(const int4* __restrict__ dst4, int nQ) {
    int t = blockIdx.x * blockDim.x + threadIdx.x;
    if (t >= nQ) return;
    int4 d = __ldg(&dst4[t]);
    atomicAdd(&g_count[d.x], 1);
    atomicAdd(&g_count[d.y], 1);
    atomicAdd(&g_count[d.z], 1);
    atomicAdd(&g_count[d.w], 1);
}
__global__ void k_hist_s(const int* __restrict__ dst, int nE) {
    int t = blockIdx.x * blockDim.x + threadIdx.x;
    int e0 = t * 4;
#pragma unroll
    for (int j = 0; j < 4; j++)
        if (e0 + j < nE) atomicAdd(&g_count[dst[e0 + j]], 1);
}

// ---- tiled coalesced single-block scan + dis + count re-zero ----------------
__global__ void __launch_bounds__(1024, 1) k_scan(int nN) {
    __shared__ int tile[STILE];     // 32 KB
    __shared__ int psum[1024];      //  4 KB
    __shared__ int carry;

    int t = threadIdx.x;
    if (t == 0) carry = 0;
    __syncthreads();

    for (int base = 0; base < nN; base += STILE) {
        int cnt = min(STILE, nN - base);

        for (int i = t; i < cnt; i += 1024) {
            int c = g_count[base + i];
            tile[i] = c;
            g_count[base + i] = 0;
            g_dis[base + i] = (c > 0) ? rsqrtf((float)c) : 0.f;
        }
        __syncthreads();

        int lo = t * 8;
        int c[8];
        int s = 0;
#pragma unroll
        for (int j = 0; j < 8; j++) {
            int idx = lo + j;
            c[j] = (idx < cnt) ? tile[idx] : 0;
            s += c[j];
        }
        psum[t] = s;
        __syncthreads();

        for (int off = 1; off < 1024; off <<= 1) {
            int u = (t >= off) ? psum[t - off] : 0;
            __syncthreads();
            psum[t] += u;
            __syncthreads();
        }

        int run = carry + psum[t] - s;
        __syncthreads();
        if (t == 1023) carry += psum[1023];

#pragma unroll
        for (int j = 0; j < 8; j++) {
            int idx = lo + j;
            if (idx < cnt) tile[idx] = run;
            run += c[j];
        }
        __syncthreads();

        for (int i = t; i < cnt; i += 1024) {
            int o = tile[i];
            g_off[base + i] = o;
            g_cur[base + i] = o;
        }
        __syncthreads();
    }
    if (t == 1023) g_off[nN] = carry;
}

// ---------------- CSR build (int4 vectorized) ----------------
__global__ void k_build4(const int4* __restrict__ src4, const int4* __restrict__ dst4, int nQ) {
    int t = blockIdx.x * blockDim.x + threadIdx.x;
    if (t >= nQ) return;
    int4 d = __ldg(&dst4[t]);
    int4 s = __ldg(&src4[t]);
    int p0 = atomicAdd(&g_cur[d.x], 1);
    int p1 = atomicAdd(&g_cur[d.y], 1);
    int p2 = atomicAdd(&g_cur[d.z], 1);
    int p3 = atomicAdd(&g_cur[d.w], 1);
    g_srcs[p0] = s.x; g_srcs[p1] = s.y; g_srcs[p2] = s.z; g_srcs[p3] = s.w;
}
__global__ void k_build_s(const int* __restrict__ src, const int* __restrict__ dst, int nE) {
    int t = blockIdx.x * blockDim.x + threadIdx.x;
    int e0 = t * 4;
    for (int j = 0; j < 4 && e0 + j < nE; j++) {
        int pos = atomicAdd(&g_cur[dst[e0 + j]], 1);
        g_srcs[pos] = src[e0 + j];
    }
}

// -------- pre-scale x: xb[n] = bf16(x[n]*dis[n]); zeros pooled --------
__global__ void k_scale_x(const float4* __restrict__ x, int nN) {
    int idx = blockIdx.x * blockDim.x + threadIdx.x;
    if (idx < N_GRAPHS_MAX * DH) g_pooled[idx] = 0.f;
    int n = idx >> 5;
    if (n >= nN) return;
    int lane = idx & 31;
    float d = g_dis[n];
    float4 v = x[(size_t)n * 32 + lane];
    __nv_bfloat162 p0 = __float22bfloat162_rn(make_float2(v.x * d, v.y * d));
    __nv_bfloat162 p1 = __float22bfloat162_rn(make_float2(v.z * d, v.w * d));
    uint2 u;
    u.x = *reinterpret_cast<unsigned*>(&p0);
    u.y = *reinterpret_cast<unsigned*>(&p1);
    reinterpret_cast<uint2*>(g_xb)[(size_t)n * 32 + lane] = u;
}

// ---------------- gather: bufA[n] = dis[n] * sum feat_pre[s]  (fp32 out) ------
__device__ __forceinline__ void acc4p(unsigned long long* a, uint4 u) {
    a[0] = addx2(a[0], pklh(u.x));
    a[1] = addx2(a[1], pklh(u.y));
    a[2] = addx2(a[2], pklh(u.z));
    a[3] = addx2(a[3], pklh(u.w));
}

__global__ void __launch_bounds__(256) k_gather(int use_x, int nN) {
    int idx = blockIdx.x * blockDim.x + threadIdx.x;
    int n = idx >> 4;
    if (n >= nN) return;
    unsigned lane = idx & 15;

    const uint4* feat = reinterpret_cast<const uint4*>(use_x ? g_xb : g_h1b);

    int b = g_off[n], e = g_off[n + 1];
    unsigned long long a[4] = {0ULL, 0ULL, 0ULL, 0ULL};

    int i = b;
    for (; i + 8 <= e; i += 8) {
        unsigned s[8];
#pragma unroll
        for (int j = 0; j < 8; j++) s[j] = (unsigned)__ldcs(&g_srcs[i + j]);
        uint4 u[8];
#pragma unroll
        for (int j = 0; j < 8; j++) u[j] = __ldg(&feat[(s[j] << 4) + lane]);
#pragma unroll
        for (int j = 0; j < 8; j++) acc4p(a, u[j]);
    }
    for (; i + 4 <= e; i += 4) {
        unsigned s0 = (unsigned)__ldcs(&g_srcs[i]);
        unsigned s1 = (unsigned)__ldcs(&g_srcs[i + 1]);
        unsigned s2 = (unsigned)__ldcs(&g_srcs[i + 2]);
        unsigned s3 = (unsigned)__ldcs(&g_srcs[i + 3]);
        uint4 u0 = __ldg(&feat[(s0 << 4) + lane]);
        uint4 u1 = __ldg(&feat[(s1 << 4) + lane]);
        uint4 u2 = __ldg(&feat[(s2 << 4) + lane]);
        uint4 u3 = __ldg(&feat[(s3 << 4) + lane]);
        acc4p(a, u0); acc4p(a, u1); acc4p(a, u2); acc4p(a, u3);
    }
    for (; i < e; i++) {
        unsigned s = (unsigned)__ldcs(&g_srcs[i]);
        uint4 u = __ldg(&feat[(s << 4) + lane]);
        acc4p(a, u);
    }

    float dn = g_dis[n];
    float o[8];
    upk2(o[0], o[1], a[0]);
    upk2(o[2], o[3], a[1]);
    upk2(o[4], o[5], a[2]);
    upk2(o[6], o[7], a[3]);
#pragma unroll
    for (int j = 0; j < 8; j++) o[j] *= dn;

    float4* orow = reinterpret_cast<float4*>(&g_bufA[(size_t)n * DH + lane * 8]);
    orow[0] = make_float4(o[0], o[1], o[2], o[3]);
    orow[1] = make_float4(o[4], o[5], o[6], o[7]);
}

// ---------------- fp16 WMMA GEMM + bias + ReLU (tile = 128 nodes) -------------
// mode 0: h1b[n] = bf16(relu(D+b) * dis[n])
// mode 1: pooling with warp-segment pre-reduction (graph_ids sorted):
//         16-row warp strips are almost always one graph -> sum rows in-warp,
//         emit 16 scalar REDs per tile instead of per-row v4 REDs.
__global__ void __launch_bounds__(256, 2)
k_gemm_hmma(const float* __restrict__ W, const float* __restrict__ b,
            const int* __restrict__ gid, int nN, int mode) {
    __shared__ __half sA[TM * ALD];         // 34.8 KB (A tile; later epilogue staging)
    __shared__ __half sW[32 * WLD];         //  8.7 KB (W k-chunk)
    __shared__ float bsh[DH];

    int tid = threadIdx.x;
    int wid = tid >> 5, lid = tid & 31;
    int node0 = blockIdx.x * TM;

    if (tid < DH / 4)
        reinterpret_cast<float4*>(bsh)[tid] = reinterpret_cast<const float4*>(b)[tid];

    // stage A tile: 128 rows x 128 k, fp32 -> fp16  (rows >= nN read zero padding)
    {
        const float4* asrc = reinterpret_cast<const float4*>(
            &g_bufA[(size_t)node0 * DH]);
        for (int i = tid; i < TM * DH / 4; i += 256) {
            int r = i >> 5;
            int c = (i & 31) << 2;
            float4 v = asrc[i];
            __half2 h0 = __floats2half2_rn(v.x, v.y);
            __half2 h1 = __floats2half2_rn(v.z, v.w);
            uint2 u;
            u.x = *reinterpret_cast<unsigned*>(&h0);
            u.y = *reinterpret_cast<unsigned*>(&h1);
            *reinterpret_cast<uint2*>(&sA[r * ALD + c]) = u;
        }
    }

    wmma::fragment<wmma::accumulator, 16, 16, 16, float> acc[8];
#pragma unroll
    for (int j = 0; j < 8; j++) wmma::fill_fragment(acc[j], 0.f);

    for (int kc = 0; kc < 4; kc++) {
        __syncthreads();
        const float4* wsrc = reinterpret_cast<const float4*>(W + (size_t)kc * 32 * DH);
        for (int i = tid; i < 32 * DH / 4; i += 256) {
            int k = i >> 5;
            int c = (i & 31) << 2;
            float4 v = wsrc[i];
            __half2 h0 = __floats2half2_rn(v.x, v.y);
            __half2 h1 = __floats2half2_rn(v.z, v.w);
            uint2 u;
            u.x = *reinterpret_cast<unsigned*>(&h0);
            u.y = *reinterpret_cast<unsigned*>(&h1);
            *reinterpret_cast<uint2*>(&sW[k * WLD + c]) = u;
        }
        __syncthreads();

#pragma unroll
        for (int ks = 0; ks < 2; ks++) {
            wmma::fragment<wmma::matrix_a, 16, 16, 16, __half, wmma::row_major> af;
            wmma::load_matrix_sync(af, &sA[(wid * 16) * ALD + kc * 32 + ks * 16], ALD);
#pragma unroll
            for (int j = 0; j < 8; j++) {
                wmma::fragment<wmma::matrix_b, 16, 16, 16, __half, wmma::row_major> bf;
                wmma::load_matrix_sync(bf, &sW[(ks * 16) * WLD + j * 16], WLD);
                wmma::mma_sync(acc[j], af, bf, acc[j]);
            }
        }
    }

    // epilogue: reuse sA as fp32 staging
    __syncthreads();
    float* stage = reinterpret_cast<float*>(sA);
    float* ob = stage + wid * (16 * OLD);

    if (mode == 0) {
        int r  = lid >> 1;
        int hc = (lid & 1) * 8;
        int nrow = node0 + wid * 16 + r;
        bool live = (nrow < nN);
        float dn = live ? g_dis[nrow] : 0.f;
#pragma unroll
        for (int j = 0; j < 8; j++) {
            wmma::store_matrix_sync(ob, acc[j], OLD, wmma::mem_row_major);
            __syncwarp();
            if (live) {
                int c0 = j * 16 + hc;
                const float* srcp = &ob[r * OLD + hc];
                float o[8];
#pragma unroll
                for (int t = 0; t < 8; t++)
                    o[t] = fmaxf(srcp[t] + bsh[c0 + t], 0.f);
                uint4 u;
                __nv_bfloat162 q0 = __float22bfloat162_rn(make_float2(o[0] * dn, o[1] * dn));
                __nv_bfloat162 q1 = __float22bfloat162_rn(make_float2(o[2] * dn, o[3] * dn));
                __nv_bfloat162 q2 = __float22bfloat162_rn(make_float2(o[4] * dn, o[5] * dn));
                __nv_bfloat162 q3 = __float22bfloat162_rn(make_float2(o[6] * dn, o[7] * dn));
                u.x = *reinterpret_cast<unsigned*>(&q0);
                u.y = *reinterpret_cast<unsigned*>(&q1);
                u.z = *reinterpret_cast<unsigned*>(&q2);
                u.w = *reinterpret_cast<unsigned*>(&q3);
                *reinterpret_cast<uint4*>(&g_h1b[(size_t)nrow * DH + c0]) = u;
            }
            __syncwarp();
        }
    } else {
        // pooling epilogue: lane = (half = lid>>4, c = lid&15)
        int base_row = node0 + wid * 16;
        int c = lid & 15;
        int half = lid >> 4;
        int g0 = __ldg(&gid[min(base_row, nN - 1)]);
        bool uniform = (base_row + 15 < nN) &&
                       (__ldg(&gid[base_row + 15]) == g0);
#pragma unroll
        for (int j = 0; j < 8; j++) {
            wmma::store_matrix_sync(ob, acc[j], OLD, wmma::mem_row_major);
            __syncwarp();
            int c0 = j * 16 + c;
            float bv = bsh[c0];
            if (uniform) {
                float s = 0.f;
#pragma unroll
                for (int rr = 0; rr < 8; rr++) {
                    int r = half * 8 + rr;
                    s += fmaxf(ob[r * OLD + c] + bv, 0.f);
                }
                s += __shfl_down_sync(0xFFFFFFFFu, s, 16);
                if (half == 0)
                    red_add_f32(&g_pooled[(size_t)g0 * DH + c0], s);
            } else {
                // graph-boundary / tail warp: per-row fallback
#pragma unroll
                for (int rr = 0; rr < 8; rr++) {
                    int r = half * 8 + rr;
                    int nrow = base_row + r;
                    if (nrow < nN) {
                        float v = fmaxf(ob[r * OLD + c] + bv, 0.f);
                        int gg = __ldg(&gid[nrow]);
                        red_add_f32(&g_pooled[(size_t)gg * DH + c0], v);
                    }
                }
            }
            __syncwarp();
        }
    }
}

// ---------------- classifier (counts via binary search on sorted gid) --------
__global__ void k_logits(const float* __restrict__ Wc, const float* __restrict__ bc,
                         const int* __restrict__ gid, float* __restrict__ out,
                         int nG, int nN) {
    __shared__ float scnt[N_GRAPHS_MAX];
    int t = threadIdx.x;
    if (t < nG) {
        int lo = 0, hi = nN;
        while (lo < hi) { int m = (lo + hi) >> 1; if (__ldg(&gid[m]) < t) lo = m + 1; else hi = m; }
        int lo2 = lo, hi2 = nN;
        while (lo2 < hi2) { int m = (lo2 + hi2) >> 1; if (__ldg(&gid[m]) < t + 1) lo2 = m + 1; else hi2 = m; }
        scnt[t] = (float)(lo2 - lo);
    }
    __syncthreads();
    int g = t >> 3, c = t & 7;
    if (g >= nG) return;
    float s = 0.f;
#pragma unroll 8
    for (int k = 0; k < DH; k++)
        s = fmaf(g_pooled[g * DH + k], __ldg(&Wc[k * 8 + c]), s);
    float cnt = fmaxf(scnt[g], 1.0f);
    out[g * 8 + c] = s / cnt + bc[c];
}

// ---------------- launch ----------------
extern "C" void kernel_launch(void* const* d_in, const int* in_sizes, int n_in,
                              void* d_out, int out_size) {
    const float* x  = (const float*)d_in[0];
    const int*   ei = (const int*)  d_in[1];
    const int*   gid= (const int*)  d_in[2];
    const float* W1 = (const float*)d_in[3];
    const float* b1 = (const float*)d_in[4];
    const float* W2 = (const float*)d_in[5];
    const float* b2 = (const float*)d_in[6];
    const float* Wc = (const float*)d_in[7];
    const float* bc = (const float*)d_in[8];
    float* out = (float*)d_out;

    int nN = in_sizes[0] / DH;
    int nE = in_sizes[1] / 2;
    int nG = out_size / 8;
    const int* src = ei;
    const int* dst = ei + nE;

    const int T = 256;
    int gN16 = (int)(((long long)nN * 16 + T - 1) / T);
    int gN32 = (int)(((long long)nN * 32 + T - 1) / T);
    int gGemm = (nN + TM - 1) / TM;

    // 1: histogram   2: tiled scan   3: x pre-scale   4: CSR build (profiled slot)
    if ((nE & 3) == 0) {
        int nQ = nE >> 2;
        int gQ = (nQ + T - 1) / T;
        k_hist4<<<gQ, T>>>((const int4*)dst, nQ);
        k_scan<<<1, 1024>>>(nN);
        k_scale_x<<<gN32, T>>>((const float4*)x, nN);
        k_build4<<<gQ, T>>>((const int4*)src, (const int4*)dst, nQ);
    } else {
        int gE4 = (nE / 4 + T) / T;
        k_hist_s<<<gE4, T>>>(dst, nE);
        k_scan<<<1, 1024>>>(nN);
        k_scale_x<<<gN32, T>>>((const float4*)x, nN);
        k_build_s<<<gE4, T>>>(src, dst, nE);
    }

    // 5: layer-1 gather   6: fp16 WMMA GEMM1 -> h1b
    k_gather<<<gN16, T>>>(1, nN);
    k_gemm_hmma<<<gGemm, T>>>(W1, b1, gid, nN, 0);

    // 7: layer-2 gather   8: fp16 WMMA GEMM2 (+low-contention pooling)
    k_gather<<<gN16, T>>>(0, nN);
    k_gemm_hmma<<<gGemm, T>>>(W2, b2, gid, nN, 1);

    // 9: classify (counts via binary search — no atomics)
    k_logits<<<1, 512>>>(Wc, bc, gid, out, nG, nN);
}